// round 16
// baseline (speedup 1.0000x reference)
#include <cuda_runtime.h>
#include <cuda_fp16.h>
#include <cstdint>

// Problem constants
#define BATCH 64
#define SEQ   512
#define DMODEL 256
#define NHEAD 4
#define HDIM  64
#define MTOT  (BATCH * SEQ)          // 32768 rows
#define DQKV  768

// ---------------- scratch (device globals; no allocation allowed) ------------
__device__ __half g_qh[MTOT * DMODEL];             // Q fp16 (pre-scaled 0.125*log2e)
__device__ __half g_kh[MTOT * DMODEL];             // K fp16
__device__ __half g_vh[MTOT * DMODEL];             // V fp16
__device__ __half g_xh[MTOT * DMODEL];             // x fp16
__device__ __half g_ah[MTOT * DMODEL];             // attn out fp16
__device__ __half g_wh[4 * DMODEL * DMODEL];       // wq|wk|wv|wo fp16
__device__ uint32_t g_adjbits[SEQ * (SEQ / 32)];   // 512 x 16 words

// ---------------- helpers ----------------------------------------------------
__device__ __forceinline__ uint32_t f2h2(float hi, float lo) {
    uint32_t r;
    asm("cvt.rn.f16x2.f32 %0, %1, %2;" : "=r"(r) : "f"(hi), "f"(lo));
    return r;
}
__device__ __forceinline__ float ex2f(float x) {
    float r;
    asm("ex2.approx.ftz.f32 %0, %1;" : "=f"(r) : "f"(x));
    return r;
}
__device__ __forceinline__ uint32_t s2u(const void* p){
    uint32_t a;
    asm("{ .reg .u64 t; cvta.to.shared.u64 t, %1; cvt.u32.u64 %0, t; }"
        : "=r"(a) : "l"(p));
    return a;
}
__device__ __forceinline__ void cp16(uint32_t dst, const void* src){
    asm volatile("cp.async.cg.shared.global [%0], [%1], 16;" :: "r"(dst), "l"(src));
}

#define MMA_F16(acc, a, b) \
    asm volatile("mma.sync.aligned.m16n8k16.row.col.f32.f16.f16.f32 " \
        "{%0,%1,%2,%3},{%4,%5,%6,%7},{%8,%9},{%0,%1,%2,%3};" \
        : "+f"((acc)[0]), "+f"((acc)[1]), "+f"((acc)[2]), "+f"((acc)[3]) \
        : "r"((a)[0]), "r"((a)[1]), "r"((a)[2]), "r"((a)[3]), \
          "r"((b)[0]), "r"((b)[1]))

#define LDSM4(d0,d1,d2,d3,a) \
    asm volatile("ldmatrix.sync.aligned.m8n8.x4.shared.b16 {%0,%1,%2,%3},[%4];" \
        : "=r"(d0), "=r"(d1), "=r"(d2), "=r"(d3) : "r"(a))
#define LDSM4T(d0,d1,d2,d3,a) \
    asm volatile("ldmatrix.sync.aligned.m8n8.x4.trans.shared.b16 {%0,%1,%2,%3},[%4];" \
        : "=r"(d0), "=r"(d1), "=r"(d2), "=r"(d3) : "r"(a))

#define CP_COMMIT() asm volatile("cp.async.commit_group;")
#define CP_WAIT1()  asm volatile("cp.async.wait_group 1;")
#define CP_WAIT0()  asm volatile("cp.async.wait_group 0;")

// ---------------- fused prologue: round x | round w | pack adj ---------------
#define NBLK_X 4096
#define NBLK_W 256
#define NBLK_A 32

__global__ __launch_bounds__(256)
void prologue(const float* __restrict__ x,
              const float* __restrict__ w0, const float* __restrict__ w1,
              const float* __restrict__ w2, const float* __restrict__ w3,
              const int* __restrict__ adj,
              __half* __restrict__ xh, __half* __restrict__ wh,
              uint32_t* __restrict__ bits)
{
    int blk = blockIdx.x;
    if (blk < NBLK_X) {
#pragma unroll
        for (int u = 0; u < 2; u++) {
            int i = blk * 512 + u * 256 + threadIdx.x;
            float4 v = ((const float4*)x)[i];
            ((uint32_t*)xh)[2*i]     = f2h2(v.y, v.x);
            ((uint32_t*)xh)[2*i + 1] = f2h2(v.w, v.z);
        }
    } else if (blk < NBLK_X + NBLK_W) {
        int lin = (blk - NBLK_X) * 256 + threadIdx.x;
        int ws = lin >> 14;
        int i  = lin & 16383;
        const float* src = ws == 0 ? w0 : ws == 1 ? w1 : ws == 2 ? w2 : w3;
        float4 v = ((const float4*)src)[i];
        int o = ws * 16384 + i;
        ((uint32_t*)wh)[2*o]     = f2h2(v.y, v.x);
        ((uint32_t*)wh)[2*o + 1] = f2h2(v.w, v.z);
    } else {
        int w = (blk - NBLK_X - NBLK_W) * 256 + threadIdx.x;
        const int* p = adj + (size_t)w * 32;
        uint32_t m = 0;
#pragma unroll
        for (int i = 0; i < 32; i++) m |= (p[i] != 0 ? 1u : 0u) << i;
        bits[w] = m;
    }
}

// ======== QKV GEMM: KC=64, 256 thr, tile 128x128, 2 CTA/SM ===================
#define GST64 72
#define T64B (128 * GST64 * 2)           // 18432
#define STG64 (2 * T64B)                 // 36864
#define PIPE64 (2 * STG64)               // 73728

__device__ __forceinline__ void cp_t64(uint32_t smdst,
        const __half* __restrict__ src, int row0, int kc, int tid)
{
#pragma unroll
    for (int it = 0; it < 4; it++) {
        int lin = it * 256 + tid;
        int r = lin >> 3, c = lin & 7;
        cp16(smdst + r * (GST64 * 2) + c * 16,
             src + (size_t)(row0 + r) * DMODEL + kc * 64 + c * 8);
    }
}

__global__ __launch_bounds__(256, 2)
void qkv_gemm(const __half* __restrict__ Ah, const __half* __restrict__ Bh,
              const float* __restrict__ b0, const float* __restrict__ b1,
              const float* __restrict__ b2,
              __half* __restrict__ Qh, __half* __restrict__ Kh,
              __half* __restrict__ Vh)
{
    extern __shared__ char sm[];
    const uint32_t smb = s2u(sm);

    const int tid  = threadIdx.x;
    const int lane = tid & 31;
    const int warp = tid >> 5;
    const int wm   = warp >> 2;
    const int wn   = warp & 3;
    const int m0   = blockIdx.y * 128;
    const int n0   = blockIdx.x * 128;

    float acc[4][4][4];
#pragma unroll
    for (int i = 0; i < 4; i++)
#pragma unroll
        for (int j = 0; j < 4; j++)
#pragma unroll
            for (int t = 0; t < 4; t++) acc[i][j][t] = 0.f;

    const int frow = lane >> 2;
    const int fcol = (lane & 3) * 2;

    const uint32_t aoff = ((wm * 64 + (lane & 15)) * GST64 + ((lane >> 4) << 3)) * 2;
    const uint32_t boff = ((wn * 32 + ((lane & 7) | ((lane >> 4) << 3))) * GST64
                           + (((lane >> 3) & 1) << 3)) * 2;

    cp_t64(smb + 0 * T64B, Ah, m0, 0, tid);
    cp_t64(smb + 1 * T64B, Bh, n0, 0, tid);
    CP_COMMIT();

#pragma unroll
    for (int kc = 0; kc < 4; kc++) {
        __syncthreads();
        if (kc < 3) {
            uint32_t st = smb + ((kc + 1) & 1) * STG64;
            cp_t64(st + 0 * T64B, Ah, m0, kc + 1, tid);
            cp_t64(st + 1 * T64B, Bh, n0, kc + 1, tid);
            CP_COMMIT();
            CP_WAIT1();
        } else {
            CP_WAIT0();
        }
        __syncthreads();

        const uint32_t stg = smb + (kc & 1) * STG64;
        const uint32_t aH = stg + aoff;
        const uint32_t bH = stg + T64B + boff;

#pragma unroll
        for (int ks = 0; ks < 4; ks++) {
            const uint32_t kso = ks * 32;
            uint32_t ah[4][4], bh[4][2];
#pragma unroll
            for (int mi = 0; mi < 4; mi++) {
                uint32_t ad = aH + mi * (16 * GST64 * 2) + kso;
                LDSM4(ah[mi][0], ah[mi][1], ah[mi][2], ah[mi][3], ad);
            }
#pragma unroll
            for (int p = 0; p < 2; p++) {
                uint32_t bd = bH + p * (16 * GST64 * 2) + kso;
                LDSM4(bh[2*p][0], bh[2*p][1], bh[2*p+1][0], bh[2*p+1][1], bd);
            }
#pragma unroll
            for (int mi = 0; mi < 4; mi++)
#pragma unroll
                for (int ni = 0; ni < 4; ni++) MMA_F16(acc[mi][ni], ah[mi], bh[ni]);
        }
    }

    const int reg = n0 >> 8;
    const float* bp = reg == 0 ? b0 : (reg == 1 ? b1 : b2);
    const int coff = reg << 8;
    __half* Ph = (reg == 0) ? Qh : ((reg == 1) ? Kh : Vh);
    const float scl = (reg == 0) ? 0.125f * 1.44269504f : 1.0f;
#pragma unroll
    for (int mi = 0; mi < 4; mi++) {
#pragma unroll
        for (int ni = 0; ni < 4; ni++) {
            int row = m0 + wm * 64 + mi * 16 + frow;
            int col = n0 + wn * 32 + ni * 8 + fcol;
            int cc = col - coff;
            float bb0 = __ldg(&bp[cc]);
            float bb1 = __ldg(&bp[cc + 1]);
            float v0 = acc[mi][ni][0] + bb0, v1 = acc[mi][ni][1] + bb1;
            float v2 = acc[mi][ni][2] + bb0, v3 = acc[mi][ni][3] + bb1;
            *(uint32_t*)&Ph[(size_t)row * DMODEL + cc] = f2h2(v1 * scl, v0 * scl);
            *(uint32_t*)&Ph[(size_t)(row + 8) * DMODEL + cc] = f2h2(v3 * scl, v2 * scl);
        }
    }
}

// ======== OUT GEMM: KC=32, 256 thr, tile 128x128, 2 CTA/SM ===================
#define GST32 40
#define T32B (128 * GST32 * 2)           // 10240
#define STG32 (2 * T32B)                 // 20480
#define PIPE32 (2 * STG32)               // 40960

__device__ __forceinline__ void cp_t32(uint32_t smdst,
        const __half* __restrict__ src, int row0, int kc, int tid)
{
#pragma unroll
    for (int it = 0; it < 2; it++) {
        int lin = it * 256 + tid;
        int r = lin >> 2, c = lin & 3;
        cp16(smdst + r * (GST32 * 2) + c * 16,
             src + (size_t)(row0 + r) * DMODEL + kc * 32 + c * 8);
    }
}

__global__ __launch_bounds__(256, 2)
void out_gemm(const __half* __restrict__ Ah, const __half* __restrict__ Bh,
              const float* __restrict__ bias, float* __restrict__ Cf)
{
    extern __shared__ char sm[];
    const uint32_t smb = s2u(sm);

    const int tid  = threadIdx.x;
    const int lane = tid & 31;
    const int warp = tid >> 5;
    const int wm   = warp >> 2;
    const int wn   = warp & 3;
    const int m0   = blockIdx.y * 128;
    const int n0   = blockIdx.x * 128;

    float acc[4][4][4];
#pragma unroll
    for (int i = 0; i < 4; i++)
#pragma unroll
        for (int j = 0; j < 4; j++)
#pragma unroll
            for (int t = 0; t < 4; t++) acc[i][j][t] = 0.f;

    const int frow = lane >> 2;
    const int fcol = (lane & 3) * 2;

    const uint32_t aoff = ((wm * 64 + (lane & 15)) * GST32 + ((lane >> 4) << 3)) * 2;
    const uint32_t boff = ((wn * 32 + ((lane & 7) | ((lane >> 4) << 3))) * GST32
                           + (((lane >> 3) & 1) << 3)) * 2;

    cp_t32(smb + 0 * T32B, Ah, m0, 0, tid);
    cp_t32(smb + 1 * T32B, Bh, n0, 0, tid);
    CP_COMMIT();

#pragma unroll
    for (int kc = 0; kc < 8; kc++) {
        __syncthreads();
        if (kc < 7) {
            uint32_t st = smb + ((kc + 1) & 1) * STG32;
            cp_t32(st + 0 * T32B, Ah, m0, kc + 1, tid);
            cp_t32(st + 1 * T32B, Bh, n0, kc + 1, tid);
            CP_COMMIT();
            CP_WAIT1();
        } else {
            CP_WAIT0();
        }
        __syncthreads();

        const uint32_t stg = smb + (kc & 1) * STG32;
        const uint32_t aH = stg + aoff;
        const uint32_t bH = stg + T32B + boff;

#pragma unroll
        for (int ks = 0; ks < 2; ks++) {
            const uint32_t kso = ks * 32;
            uint32_t ah[4][4], bh[4][2];
#pragma unroll
            for (int mi = 0; mi < 4; mi++) {
                uint32_t ad = aH + mi * (16 * GST32 * 2) + kso;
                LDSM4(ah[mi][0], ah[mi][1], ah[mi][2], ah[mi][3], ad);
            }
#pragma unroll
            for (int p = 0; p < 2; p++) {
                uint32_t bd = bH + p * (16 * GST32 * 2) + kso;
                LDSM4(bh[2*p][0], bh[2*p][1], bh[2*p+1][0], bh[2*p+1][1], bd);
            }
#pragma unroll
            for (int mi = 0; mi < 4; mi++)
#pragma unroll
                for (int ni = 0; ni < 4; ni++) MMA_F16(acc[mi][ni], ah[mi], bh[ni]);
        }
    }

#pragma unroll
    for (int mi = 0; mi < 4; mi++) {
#pragma unroll
        for (int ni = 0; ni < 4; ni++) {
            int row = m0 + wm * 64 + mi * 16 + frow;
            int col = n0 + wn * 32 + ni * 8 + fcol;
            float bb0 = __ldg(&bias[col]);
            float bb1 = __ldg(&bias[col + 1]);
            *(float2*)&Cf[(size_t)row * DMODEL + col] =
                make_float2(acc[mi][ni][0] + bb0, acc[mi][ni][1] + bb1);
            *(float2*)&Cf[(size_t)(row + 8) * DMODEL + col] =
                make_float2(acc[mi][ni][2] + bb0, acc[mi][ni][3] + bb1);
        }
    }
}

// ------- fp16 masked flash attention (128-key stages, hoisted Q, MUFU ex2) ---
#define QST 72
#define QTILE 18432                    // 128*72*2
#define TKV2 18432                     // 128 keys * 72 * 2 (per K or V)
#define STAGE2 (2 * TKV2)              // 36864: Kh|Vh
#define OFF_KV QTILE                   // 18432
#define ATTN7_SMEM (OFF_KV + 2 * STAGE2)   // 92160

__global__ __launch_bounds__(256, 2)
void attn_mma(const __half* __restrict__ Qh,
              const __half* __restrict__ Kh, const __half* __restrict__ Vh,
              const uint32_t* __restrict__ adjbits, __half* __restrict__ Oh)
{
    extern __shared__ char sm[];
    const uint32_t smu = s2u(sm);

    const int tid = threadIdx.x, lane = tid & 31, warp = tid >> 5;
    const int q0 = blockIdx.x * 128;
    const int h = blockIdx.y, b = blockIdx.z;
    const size_t rbase = (size_t)b * SEQ;
    const int hc = h * HDIM;
    const int frow = lane >> 2, fcol = (lane & 3) * 2;

    const uint32_t patA = (((lane & 15)) * QST + ((lane >> 4) << 3)) * 2;
    const uint32_t patB = ((((lane & 7) | ((lane >> 4) << 3))) * QST
                           + (((lane >> 3) & 1) << 3)) * 2;

    auto cp_kv = [&](int st, int t){
        uint32_t sb = smu + OFF_KV + st * STAGE2;
#pragma unroll
        for (int it = 0; it < 4; it++) {
            int lin = it * 256 + tid;
            int r = lin >> 3, c = lin & 7;
            size_t g = (rbase + t * 128 + r) * DMODEL + hc + c * 8;
            uint32_t d = r * (QST * 2) + c * 16;
            cp16(sb + d, Kh + g);
            cp16(sb + TKV2 + d, Vh + g);
        }
    };

    // prologue: Q + kv0 (group 0); kv1 (group 1); then Q frags -> registers
    {
#pragma unroll
        for (int it = 0; it < 4; it++) {
            int lin = it * 256 + tid;
            int r = lin >> 3, c = lin & 7;
            size_t g = (rbase + q0 + r) * DMODEL + hc + c * 8;
            cp16(smu + r * (QST * 2) + c * 16, Qh + g);
        }
        cp_kv(0, 0);
        CP_COMMIT();
        cp_kv(1, 1);
        CP_COMMIT();
    }
    CP_WAIT1();          // group 0 (Q + kv0) complete
    __syncthreads();

    // hoisted, tile-invariant Q fragments (16 regs)
    uint32_t qa[4][4];
#pragma unroll
    for (int ks = 0; ks < 4; ks++) {
        uint32_t qadr = smu + warp * (16 * QST * 2) + patA + ks * 32;
        LDSM4(qa[ks][0], qa[ks][1], qa[ks][2], qa[ks][3], qadr);
    }

    float m0r = -1e30f, m1r = -1e30f, l0r = 0.f, l1r = 0.f;
    float accO[8][4];
#pragma unroll
    for (int i = 0; i < 8; i++)
#pragma unroll
        for (int j = 0; j < 4; j++) accO[i][j] = 0.f;

    const int grow = warp * 16 + frow;

#pragma unroll
    for (int t = 0; t < 4; t++) {
        uint4 a0 = *(const uint4*)&adjbits[(size_t)(q0 + grow) * 16 + t * 4];
        uint4 a1 = *(const uint4*)&adjbits[(size_t)(q0 + grow + 8) * 16 + t * 4];

        const uint32_t kvb = smu + OFF_KV + (t & 1) * STAGE2;
        const uint32_t w0a[4] = {a0.x, a0.y, a0.z, a0.w};
        const uint32_t w1a[4] = {a1.x, a1.y, a1.z, a1.w};

#pragma unroll
        for (int hf = 0; hf < 2; hf++) {
            const uint32_t koff = hf * (64 * QST * 2);

            float s[8][4];
#pragma unroll
            for (int i = 0; i < 8; i++)
#pragma unroll
                for (int j = 0; j < 4; j++) s[i][j] = 0.f;

#pragma unroll
            for (int ks = 0; ks < 4; ks++) {
                const uint32_t kso = ks * 32;
                uint32_t bh[8][2];
#pragma unroll
                for (int p = 0; p < 4; p++) {
                    uint32_t kd = kvb + koff + p * (16 * QST * 2) + patB + kso;
                    LDSM4(bh[2*p][0], bh[2*p][1], bh[2*p+1][0], bh[2*p+1][1], kd);
                }
#pragma unroll
                for (int ni = 0; ni < 8; ni++) MMA_F16(s[ni], qa[ks], bh[ni]);
            }

            const uint32_t w0p[2] = {w0a[hf*2], w0a[hf*2+1]};
            const uint32_t w1p[2] = {w1a[hf*2], w1a[hf*2+1]};
            float mx0 = -1e30f, mx1 = -1e30f;
#pragma unroll
            for (int ni = 0; ni < 8; ni++) {
                int col = ni * 8 + fcol;
                uint32_t w0 = w0p[ni >> 2], w1 = w1p[ni >> 2];
                if (!((w0 >> (col & 31)) & 1u))       s[ni][0] = -1e30f;
                if (!((w0 >> ((col + 1) & 31)) & 1u)) s[ni][1] = -1e30f;
                if (!((w1 >> (col & 31)) & 1u))       s[ni][2] = -1e30f;
                if (!((w1 >> ((col + 1) & 31)) & 1u)) s[ni][3] = -1e30f;
                mx0 = fmaxf(mx0, fmaxf(s[ni][0], s[ni][1]));
                mx1 = fmaxf(mx1, fmaxf(s[ni][2], s[ni][3]));
            }
            mx0 = fmaxf(mx0, __shfl_xor_sync(0xffffffffu, mx0, 1));
            mx0 = fmaxf(mx0, __shfl_xor_sync(0xffffffffu, mx0, 2));
            mx1 = fmaxf(mx1, __shfl_xor_sync(0xffffffffu, mx1, 1));
            mx1 = fmaxf(mx1, __shfl_xor_sync(0xffffffffu, mx1, 2));
            float mn0 = fmaxf(m0r, mx0), mn1 = fmaxf(m1r, mx1);
            float sc0 = ex2f(m0r - mn0), sc1 = ex2f(m1r - mn1);
            float ts0 = 0.f, ts1 = 0.f;
#pragma unroll
            for (int ni = 0; ni < 8; ni++) {
                s[ni][0] = ex2f(s[ni][0] - mn0);
                s[ni][1] = ex2f(s[ni][1] - mn0);
                s[ni][2] = ex2f(s[ni][2] - mn1);
                s[ni][3] = ex2f(s[ni][3] - mn1);
                ts0 += s[ni][0] + s[ni][1];
                ts1 += s[ni][2] + s[ni][3];
            }
            ts0 += __shfl_xor_sync(0xffffffffu, ts0, 1);
            ts0 += __shfl_xor_sync(0xffffffffu, ts0, 2);
            ts1 += __shfl_xor_sync(0xffffffffu, ts1, 1);
            ts1 += __shfl_xor_sync(0xffffffffu, ts1, 2);
            l0r = l0r * sc0 + ts0;  l1r = l1r * sc1 + ts1;
            m0r = mn0;  m1r = mn1;
#pragma unroll
            for (int ni = 0; ni < 8; ni++) {
                accO[ni][0] *= sc0; accO[ni][1] *= sc0;
                accO[ni][2] *= sc1; accO[ni][3] *= sc1;
            }

#pragma unroll
            for (int kt = 0; kt < 4; kt++) {
                uint32_t pah[4];
                pah[0] = f2h2(s[2*kt][1],   s[2*kt][0]);
                pah[1] = f2h2(s[2*kt][3],   s[2*kt][2]);
                pah[2] = f2h2(s[2*kt+1][1], s[2*kt+1][0]);
                pah[3] = f2h2(s[2*kt+1][3], s[2*kt+1][2]);
                uint32_t vh[8][2];
#pragma unroll
                for (int p = 0; p < 4; p++) {
                    uint32_t vd = kvb + TKV2 + koff + kt * (16 * QST * 2) + patA + p * 32;
                    LDSM4T(vh[2*p][0], vh[2*p][1], vh[2*p+1][0], vh[2*p+1][1], vd);
                }
#pragma unroll
                for (int d = 0; d < 8; d++) MMA_F16(accO[d], pah, vh[d]);
            }
        }

        // pipeline: free this stage, prefetch t+2, ensure t+1 ready
        __syncthreads();
        if (t < 2) { cp_kv(t & 1, t + 2); CP_COMMIT(); }
        if (t < 3) { CP_WAIT1(); __syncthreads(); }
    }

    float i0 = 1.f / l0r, i1 = 1.f / l1r;
    const size_t obase = rbase * DMODEL;
    const int growg = q0 + warp * 16 + frow;
#pragma unroll
    for (int ni = 0; ni < 8; ni++) {
        int col = hc + ni * 8 + fcol;
        *(uint32_t*)&Oh[obase + (size_t)growg * DMODEL + col] =
            f2h2(accO[ni][1] * i0, accO[ni][0] * i0);
        *(uint32_t*)&Oh[obase + (size_t)(growg + 8) * DMODEL + col] =
            f2h2(accO[ni][3] * i1, accO[ni][2] * i1);
    }
}

// ---------------- launch -----------------------------------------------------
extern "C" void kernel_launch(void* const* d_in, const int* in_sizes, int n_in,
                              void* d_out, int out_size)
{
    const float* x  = (const float*)d_in[0];
    const int*   adj = (const int*) d_in[1];
    const float* wq = (const float*)d_in[2];
    const float* bq = (const float*)d_in[3];
    const float* wk = (const float*)d_in[4];
    const float* bk = (const float*)d_in[5];
    const float* wv = (const float*)d_in[6];
    const float* bv = (const float*)d_in[7];
    const float* wo = (const float*)d_in[8];
    const float* bo = (const float*)d_in[9];
    float* out = (float*)d_out;

    __half *gqh, *gkh, *gvh, *gxh, *gah, *gwh;
    uint32_t* gab;
    cudaGetSymbolAddress((void**)&gqh, g_qh);
    cudaGetSymbolAddress((void**)&gkh, g_kh);
    cudaGetSymbolAddress((void**)&gvh, g_vh);
    cudaGetSymbolAddress((void**)&gxh, g_xh);
    cudaGetSymbolAddress((void**)&gah, g_ah);
    cudaGetSymbolAddress((void**)&gwh, g_wh);
    cudaGetSymbolAddress((void**)&gab, g_adjbits);

    cudaFuncSetAttribute(qkv_gemm,
                         cudaFuncAttributeMaxDynamicSharedMemorySize, PIPE64);
    cudaFuncSetAttribute(out_gemm,
                         cudaFuncAttributeMaxDynamicSharedMemorySize, PIPE32);
    cudaFuncSetAttribute(attn_mma,
                         cudaFuncAttributeMaxDynamicSharedMemorySize, ATTN7_SMEM);

    const int WSZ = DMODEL * DMODEL;           // 65536

    prologue<<<NBLK_X + NBLK_W + NBLK_A, 256>>>(
        x, wq, wk, wv, wo, adj, gxh, gwh, gab);

    qkv_gemm<<<dim3(DQKV / 128, MTOT / 128), 256, PIPE64>>>(
        gxh, gwh, bq, bk, bv, gqh, gkh, gvh);

    attn_mma<<<dim3(SEQ / 128, NHEAD, BATCH), 256, ATTN7_SMEM>>>(
        gqh, gkh, gvh, gab, gah);

    out_gemm<<<dim3(DMODEL / 128, MTOT / 128), 256, PIPE32>>>(
        gah, gwh + 3*WSZ, bo, out);
}

// round 17
// speedup vs baseline: 1.4646x; 1.4646x over previous
#include <cuda_runtime.h>
#include <cuda_fp16.h>
#include <cstdint>

// Problem constants
#define BATCH 64
#define SEQ   512
#define DMODEL 256
#define NHEAD 4
#define HDIM  64
#define MTOT  (BATCH * SEQ)          // 32768 rows
#define DQKV  768

// ---------------- scratch (device globals; no allocation allowed) ------------
__device__ __half g_qh[MTOT * DMODEL];             // Q fp16 (pre-scaled 0.125*log2e)
__device__ __half g_kh[MTOT * DMODEL];             // K fp16
__device__ __half g_vh[MTOT * DMODEL];             // V fp16
__device__ __half g_xh[MTOT * DMODEL];             // x fp16
__device__ __half g_ah[MTOT * DMODEL];             // attn out fp16
__device__ __half g_wh[4 * DMODEL * DMODEL];       // wq|wk|wv|wo fp16
__device__ uint32_t g_adjbits[SEQ * (SEQ / 32)];   // 512 x 16 words

// ---------------- helpers ----------------------------------------------------
__device__ __forceinline__ uint32_t f2h2(float hi, float lo) {
    uint32_t r;
    asm("cvt.rn.f16x2.f32 %0, %1, %2;" : "=r"(r) : "f"(hi), "f"(lo));
    return r;
}
__device__ __forceinline__ uint32_t s2u(const void* p){
    uint32_t a;
    asm("{ .reg .u64 t; cvta.to.shared.u64 t, %1; cvt.u32.u64 %0, t; }"
        : "=r"(a) : "l"(p));
    return a;
}
__device__ __forceinline__ void cp16(uint32_t dst, const void* src){
    asm volatile("cp.async.cg.shared.global [%0], [%1], 16;" :: "r"(dst), "l"(src));
}

#define MMA_F16(acc, a, b) \
    asm volatile("mma.sync.aligned.m16n8k16.row.col.f32.f16.f16.f32 " \
        "{%0,%1,%2,%3},{%4,%5,%6,%7},{%8,%9},{%0,%1,%2,%3};" \
        : "+f"((acc)[0]), "+f"((acc)[1]), "+f"((acc)[2]), "+f"((acc)[3]) \
        : "r"((a)[0]), "r"((a)[1]), "r"((a)[2]), "r"((a)[3]), \
          "r"((b)[0]), "r"((b)[1]))

#define LDSM4(d0,d1,d2,d3,a) \
    asm volatile("ldmatrix.sync.aligned.m8n8.x4.shared.b16 {%0,%1,%2,%3},[%4];" \
        : "=r"(d0), "=r"(d1), "=r"(d2), "=r"(d3) : "r"(a))
#define LDSM4T(d0,d1,d2,d3,a) \
    asm volatile("ldmatrix.sync.aligned.m8n8.x4.trans.shared.b16 {%0,%1,%2,%3},[%4];" \
        : "=r"(d0), "=r"(d1), "=r"(d2), "=r"(d3) : "r"(a))

#define CP_COMMIT() asm volatile("cp.async.commit_group;")
#define CP_WAIT1()  asm volatile("cp.async.wait_group 1;")
#define CP_WAIT0()  asm volatile("cp.async.wait_group 0;")

// ---------------- fused prologue: round x | round w | pack adj ---------------
#define NBLK_X 4096
#define NBLK_W 256
#define NBLK_A 32

__global__ __launch_bounds__(256)
void prologue(const float* __restrict__ x,
              const float* __restrict__ w0, const float* __restrict__ w1,
              const float* __restrict__ w2, const float* __restrict__ w3,
              const int* __restrict__ adj,
              __half* __restrict__ xh, __half* __restrict__ wh,
              uint32_t* __restrict__ bits)
{
    int blk = blockIdx.x;
    if (blk < NBLK_X) {
#pragma unroll
        for (int u = 0; u < 2; u++) {
            int i = blk * 512 + u * 256 + threadIdx.x;
            float4 v = ((const float4*)x)[i];
            ((uint32_t*)xh)[2*i]     = f2h2(v.y, v.x);
            ((uint32_t*)xh)[2*i + 1] = f2h2(v.w, v.z);
        }
    } else if (blk < NBLK_X + NBLK_W) {
        int lin = (blk - NBLK_X) * 256 + threadIdx.x;
        int ws = lin >> 14;
        int i  = lin & 16383;
        const float* src = ws == 0 ? w0 : ws == 1 ? w1 : ws == 2 ? w2 : w3;
        float4 v = ((const float4*)src)[i];
        int o = ws * 16384 + i;
        ((uint32_t*)wh)[2*o]     = f2h2(v.y, v.x);
        ((uint32_t*)wh)[2*o + 1] = f2h2(v.w, v.z);
    } else {
        int w = (blk - NBLK_X - NBLK_W) * 256 + threadIdx.x;
        const int* p = adj + (size_t)w * 32;
        uint32_t m = 0;
#pragma unroll
        for (int i = 0; i < 32; i++) m |= (p[i] != 0 ? 1u : 0u) << i;
        bits[w] = m;
    }
}

// ======== QKV GEMM: KC=64, 256 thr, tile 128x128, 2 CTA/SM ===================
#define GST64 72
#define T64B (128 * GST64 * 2)           // 18432
#define STG64 (2 * T64B)                 // 36864
#define PIPE64 (2 * STG64)               // 73728

__device__ __forceinline__ void cp_t64(uint32_t smdst,
        const __half* __restrict__ src, int row0, int kc, int tid)
{
#pragma unroll
    for (int it = 0; it < 4; it++) {
        int lin = it * 256 + tid;
        int r = lin >> 3, c = lin & 7;
        cp16(smdst + r * (GST64 * 2) + c * 16,
             src + (size_t)(row0 + r) * DMODEL + kc * 64 + c * 8);
    }
}

__global__ __launch_bounds__(256, 2)
void qkv_gemm(const __half* __restrict__ Ah, const __half* __restrict__ Bh,
              const float* __restrict__ b0, const float* __restrict__ b1,
              const float* __restrict__ b2,
              __half* __restrict__ Qh, __half* __restrict__ Kh,
              __half* __restrict__ Vh)
{
    extern __shared__ char sm[];
    const uint32_t smb = s2u(sm);

    const int tid  = threadIdx.x;
    const int lane = tid & 31;
    const int warp = tid >> 5;
    const int wm   = warp >> 2;
    const int wn   = warp & 3;
    const int m0   = blockIdx.y * 128;
    const int n0   = blockIdx.x * 128;

    float acc[4][4][4];
#pragma unroll
    for (int i = 0; i < 4; i++)
#pragma unroll
        for (int j = 0; j < 4; j++)
#pragma unroll
            for (int t = 0; t < 4; t++) acc[i][j][t] = 0.f;

    const int frow = lane >> 2;
    const int fcol = (lane & 3) * 2;

    const uint32_t aoff = ((wm * 64 + (lane & 15)) * GST64 + ((lane >> 4) << 3)) * 2;
    const uint32_t boff = ((wn * 32 + ((lane & 7) | ((lane >> 4) << 3))) * GST64
                           + (((lane >> 3) & 1) << 3)) * 2;

    cp_t64(smb + 0 * T64B, Ah, m0, 0, tid);
    cp_t64(smb + 1 * T64B, Bh, n0, 0, tid);
    CP_COMMIT();

#pragma unroll
    for (int kc = 0; kc < 4; kc++) {
        __syncthreads();
        if (kc < 3) {
            uint32_t st = smb + ((kc + 1) & 1) * STG64;
            cp_t64(st + 0 * T64B, Ah, m0, kc + 1, tid);
            cp_t64(st + 1 * T64B, Bh, n0, kc + 1, tid);
            CP_COMMIT();
            CP_WAIT1();
        } else {
            CP_WAIT0();
        }
        __syncthreads();

        const uint32_t stg = smb + (kc & 1) * STG64;
        const uint32_t aH = stg + aoff;
        const uint32_t bH = stg + T64B + boff;

#pragma unroll
        for (int ks = 0; ks < 4; ks++) {
            const uint32_t kso = ks * 32;
            uint32_t ah[4][4], bh[4][2];
#pragma unroll
            for (int mi = 0; mi < 4; mi++) {
                uint32_t ad = aH + mi * (16 * GST64 * 2) + kso;
                LDSM4(ah[mi][0], ah[mi][1], ah[mi][2], ah[mi][3], ad);
            }
#pragma unroll
            for (int p = 0; p < 2; p++) {
                uint32_t bd = bH + p * (16 * GST64 * 2) + kso;
                LDSM4(bh[2*p][0], bh[2*p][1], bh[2*p+1][0], bh[2*p+1][1], bd);
            }
#pragma unroll
            for (int mi = 0; mi < 4; mi++)
#pragma unroll
                for (int ni = 0; ni < 4; ni++) MMA_F16(acc[mi][ni], ah[mi], bh[ni]);
        }
    }

    const int reg = n0 >> 8;
    const float* bp = reg == 0 ? b0 : (reg == 1 ? b1 : b2);
    const int coff = reg << 8;
    __half* Ph = (reg == 0) ? Qh : ((reg == 1) ? Kh : Vh);
    const float scl = (reg == 0) ? 0.125f * 1.44269504f : 1.0f;
#pragma unroll
    for (int mi = 0; mi < 4; mi++) {
#pragma unroll
        for (int ni = 0; ni < 4; ni++) {
            int row = m0 + wm * 64 + mi * 16 + frow;
            int col = n0 + wn * 32 + ni * 8 + fcol;
            int cc = col - coff;
            float bb0 = __ldg(&bp[cc]);
            float bb1 = __ldg(&bp[cc + 1]);
            float v0 = acc[mi][ni][0] + bb0, v1 = acc[mi][ni][1] + bb1;
            float v2 = acc[mi][ni][2] + bb0, v3 = acc[mi][ni][3] + bb1;
            *(uint32_t*)&Ph[(size_t)row * DMODEL + cc] = f2h2(v1 * scl, v0 * scl);
            *(uint32_t*)&Ph[(size_t)(row + 8) * DMODEL + cc] = f2h2(v3 * scl, v2 * scl);
        }
    }
}

// ======== OUT GEMM: KC=32, 256 thr, tile 128x128, 2 CTA/SM ===================
#define GST32 40
#define T32B (128 * GST32 * 2)           // 10240
#define STG32 (2 * T32B)                 // 20480
#define PIPE32 (2 * STG32)               // 40960

__device__ __forceinline__ void cp_t32(uint32_t smdst,
        const __half* __restrict__ src, int row0, int kc, int tid)
{
#pragma unroll
    for (int it = 0; it < 2; it++) {
        int lin = it * 256 + tid;
        int r = lin >> 2, c = lin & 3;
        cp16(smdst + r * (GST32 * 2) + c * 16,
             src + (size_t)(row0 + r) * DMODEL + kc * 32 + c * 8);
    }
}

__global__ __launch_bounds__(256, 2)
void out_gemm(const __half* __restrict__ Ah, const __half* __restrict__ Bh,
              const float* __restrict__ bias, float* __restrict__ Cf)
{
    extern __shared__ char sm[];
    const uint32_t smb = s2u(sm);

    const int tid  = threadIdx.x;
    const int lane = tid & 31;
    const int warp = tid >> 5;
    const int wm   = warp >> 2;
    const int wn   = warp & 3;
    const int m0   = blockIdx.y * 128;
    const int n0   = blockIdx.x * 128;

    float acc[4][4][4];
#pragma unroll
    for (int i = 0; i < 4; i++)
#pragma unroll
        for (int j = 0; j < 4; j++)
#pragma unroll
            for (int t = 0; t < 4; t++) acc[i][j][t] = 0.f;

    const int frow = lane >> 2;
    const int fcol = (lane & 3) * 2;

    const uint32_t aoff = ((wm * 64 + (lane & 15)) * GST32 + ((lane >> 4) << 3)) * 2;
    const uint32_t boff = ((wn * 32 + ((lane & 7) | ((lane >> 4) << 3))) * GST32
                           + (((lane >> 3) & 1) << 3)) * 2;

    cp_t32(smb + 0 * T32B, Ah, m0, 0, tid);
    cp_t32(smb + 1 * T32B, Bh, n0, 0, tid);
    CP_COMMIT();

#pragma unroll
    for (int kc = 0; kc < 8; kc++) {
        __syncthreads();
        if (kc < 7) {
            uint32_t st = smb + ((kc + 1) & 1) * STG32;
            cp_t32(st + 0 * T32B, Ah, m0, kc + 1, tid);
            cp_t32(st + 1 * T32B, Bh, n0, kc + 1, tid);
            CP_COMMIT();
            CP_WAIT1();
        } else {
            CP_WAIT0();
        }
        __syncthreads();

        const uint32_t stg = smb + (kc & 1) * STG32;
        const uint32_t aH = stg + aoff;
        const uint32_t bH = stg + T32B + boff;

#pragma unroll
        for (int ks = 0; ks < 2; ks++) {
            const uint32_t kso = ks * 32;
            uint32_t ah[4][4], bh[4][2];
#pragma unroll
            for (int mi = 0; mi < 4; mi++) {
                uint32_t ad = aH + mi * (16 * GST32 * 2) + kso;
                LDSM4(ah[mi][0], ah[mi][1], ah[mi][2], ah[mi][3], ad);
            }
#pragma unroll
            for (int p = 0; p < 2; p++) {
                uint32_t bd = bH + p * (16 * GST32 * 2) + kso;
                LDSM4(bh[2*p][0], bh[2*p][1], bh[2*p+1][0], bh[2*p+1][1], bd);
            }
#pragma unroll
            for (int mi = 0; mi < 4; mi++)
#pragma unroll
                for (int ni = 0; ni < 4; ni++) MMA_F16(acc[mi][ni], ah[mi], bh[ni]);
        }
    }

#pragma unroll
    for (int mi = 0; mi < 4; mi++) {
#pragma unroll
        for (int ni = 0; ni < 4; ni++) {
            int row = m0 + wm * 64 + mi * 16 + frow;
            int col = n0 + wn * 32 + ni * 8 + fcol;
            float bb0 = __ldg(&bias[col]);
            float bb1 = __ldg(&bias[col + 1]);
            *(float2*)&Cf[(size_t)row * DMODEL + col] =
                make_float2(acc[mi][ni][0] + bb0, acc[mi][ni][1] + bb1);
            *(float2*)&Cf[(size_t)(row + 8) * DMODEL + col] =
                make_float2(acc[mi][ni][2] + bb0, acc[mi][ni][3] + bb1);
        }
    }
}

// ------- fp16 masked flash attention (R15 pipeline + hoisted Q frags) --------
#define QST 72
#define QTILE 18432                    // 128*72*2
#define TKV2 18432                     // 128 keys * 72 * 2 (per K or V)
#define STAGE2 (2 * TKV2)              // 36864: Kh|Vh
#define OFF_KV QTILE                   // 18432
#define ATTN7_SMEM (OFF_KV + 2 * STAGE2)   // 92160

__global__ __launch_bounds__(256, 2)
void attn_mma(const __half* __restrict__ Qh,
              const __half* __restrict__ Kh, const __half* __restrict__ Vh,
              const uint32_t* __restrict__ adjbits, __half* __restrict__ Oh)
{
    extern __shared__ char sm[];
    const uint32_t smu = s2u(sm);

    const int tid = threadIdx.x, lane = tid & 31, warp = tid >> 5;
    const int q0 = blockIdx.x * 128;
    const int h = blockIdx.y, b = blockIdx.z;
    const size_t rbase = (size_t)b * SEQ;
    const int hc = h * HDIM;
    const int frow = lane >> 2, fcol = (lane & 3) * 2;

    const uint32_t patA = (((lane & 15)) * QST + ((lane >> 4) << 3)) * 2;
    const uint32_t patB = ((((lane & 7) | ((lane >> 4) << 3))) * QST
                           + (((lane >> 3) & 1) << 3)) * 2;

    auto cp_kv = [&](int st, int t){
        uint32_t sb = smu + OFF_KV + st * STAGE2;
#pragma unroll
        for (int it = 0; it < 4; it++) {
            int lin = it * 256 + tid;
            int r = lin >> 3, c = lin & 7;
            size_t g = (rbase + t * 128 + r) * DMODEL + hc + c * 8;
            uint32_t d = r * (QST * 2) + c * 16;
            cp16(sb + d, Kh + g);
            cp16(sb + TKV2 + d, Vh + g);
        }
    };

    // prologue: Q + kv0 (group 0); then hoist Q fragments into registers
    {
#pragma unroll
        for (int it = 0; it < 4; it++) {
            int lin = it * 256 + tid;
            int r = lin >> 3, c = lin & 7;
            size_t g = (rbase + q0 + r) * DMODEL + hc + c * 8;
            cp16(smu + r * (QST * 2) + c * 16, Qh + g);
        }
        cp_kv(0, 0);
        CP_COMMIT();
    }
    CP_WAIT0();          // Q + kv0 resident
    __syncthreads();

    uint32_t qa[4][4];   // tile-invariant Q fragments (16 regs)
#pragma unroll
    for (int ks = 0; ks < 4; ks++) {
        uint32_t qadr = smu + warp * (16 * QST * 2) + patA + ks * 32;
        LDSM4(qa[ks][0], qa[ks][1], qa[ks][2], qa[ks][3], qadr);
    }

    float m0r = -1e30f, m1r = -1e30f, l0r = 0.f, l1r = 0.f;
    float accO[8][4];
#pragma unroll
    for (int i = 0; i < 8; i++)
#pragma unroll
        for (int j = 0; j < 4; j++) accO[i][j] = 0.f;

    const int grow = warp * 16 + frow;

#pragma unroll
    for (int t = 0; t < 4; t++) {
        uint4 a0 = *(const uint4*)&adjbits[(size_t)(q0 + grow) * 16 + t * 4];
        uint4 a1 = *(const uint4*)&adjbits[(size_t)(q0 + grow + 8) * 16 + t * 4];

        __syncthreads();
        if (t < 3) {
            cp_kv((t + 1) & 1, t + 1);
            CP_COMMIT();
            CP_WAIT1();
        } else {
            CP_WAIT0();
        }
        __syncthreads();

        const uint32_t kvb = smu + OFF_KV + (t & 1) * STAGE2;
        const uint32_t w0a[4] = {a0.x, a0.y, a0.z, a0.w};
        const uint32_t w1a[4] = {a1.x, a1.y, a1.z, a1.w};

#pragma unroll
        for (int hf = 0; hf < 2; hf++) {
            const uint32_t koff = hf * (64 * QST * 2);

            float s[8][4];
#pragma unroll
            for (int i = 0; i < 8; i++)
#pragma unroll
                for (int j = 0; j < 4; j++) s[i][j] = 0.f;

#pragma unroll
            for (int ks = 0; ks < 4; ks++) {
                const uint32_t kso = ks * 32;
                uint32_t bh[8][2];
#pragma unroll
                for (int p = 0; p < 4; p++) {
                    uint32_t kd = kvb + koff + p * (16 * QST * 2) + patB + kso;
                    LDSM4(bh[2*p][0], bh[2*p][1], bh[2*p+1][0], bh[2*p+1][1], kd);
                }
#pragma unroll
                for (int ni = 0; ni < 8; ni++) MMA_F16(s[ni], qa[ks], bh[ni]);
            }

            const uint32_t w0p[2] = {w0a[hf*2], w0a[hf*2+1]};
            const uint32_t w1p[2] = {w1a[hf*2], w1a[hf*2+1]};
            float mx0 = -1e30f, mx1 = -1e30f;
#pragma unroll
            for (int ni = 0; ni < 8; ni++) {
                int col = ni * 8 + fcol;
                uint32_t w0 = w0p[ni >> 2], w1 = w1p[ni >> 2];
                if (!((w0 >> (col & 31)) & 1u))       s[ni][0] = -1e30f;
                if (!((w0 >> ((col + 1) & 31)) & 1u)) s[ni][1] = -1e30f;
                if (!((w1 >> (col & 31)) & 1u))       s[ni][2] = -1e30f;
                if (!((w1 >> ((col + 1) & 31)) & 1u)) s[ni][3] = -1e30f;
                mx0 = fmaxf(mx0, fmaxf(s[ni][0], s[ni][1]));
                mx1 = fmaxf(mx1, fmaxf(s[ni][2], s[ni][3]));
            }
            mx0 = fmaxf(mx0, __shfl_xor_sync(0xffffffffu, mx0, 1));
            mx0 = fmaxf(mx0, __shfl_xor_sync(0xffffffffu, mx0, 2));
            mx1 = fmaxf(mx1, __shfl_xor_sync(0xffffffffu, mx1, 1));
            mx1 = fmaxf(mx1, __shfl_xor_sync(0xffffffffu, mx1, 2));
            float mn0 = fmaxf(m0r, mx0), mn1 = fmaxf(m1r, mx1);
            float sc0 = exp2f(m0r - mn0), sc1 = exp2f(m1r - mn1);
            float ts0 = 0.f, ts1 = 0.f;
#pragma unroll
            for (int ni = 0; ni < 8; ni++) {
                s[ni][0] = exp2f(s[ni][0] - mn0);
                s[ni][1] = exp2f(s[ni][1] - mn0);
                s[ni][2] = exp2f(s[ni][2] - mn1);
                s[ni][3] = exp2f(s[ni][3] - mn1);
                ts0 += s[ni][0] + s[ni][1];
                ts1 += s[ni][2] + s[ni][3];
            }
            ts0 += __shfl_xor_sync(0xffffffffu, ts0, 1);
            ts0 += __shfl_xor_sync(0xffffffffu, ts0, 2);
            ts1 += __shfl_xor_sync(0xffffffffu, ts1, 1);
            ts1 += __shfl_xor_sync(0xffffffffu, ts1, 2);
            l0r = l0r * sc0 + ts0;  l1r = l1r * sc1 + ts1;
            m0r = mn0;  m1r = mn1;
#pragma unroll
            for (int ni = 0; ni < 8; ni++) {
                accO[ni][0] *= sc0; accO[ni][1] *= sc0;
                accO[ni][2] *= sc1; accO[ni][3] *= sc1;
            }

#pragma unroll
            for (int kt = 0; kt < 4; kt++) {
                uint32_t pah[4];
                pah[0] = f2h2(s[2*kt][1],   s[2*kt][0]);
                pah[1] = f2h2(s[2*kt][3],   s[2*kt][2]);
                pah[2] = f2h2(s[2*kt+1][1], s[2*kt+1][0]);
                pah[3] = f2h2(s[2*kt+1][3], s[2*kt+1][2]);
                uint32_t vh[8][2];
#pragma unroll
                for (int p = 0; p < 4; p++) {
                    uint32_t vd = kvb + TKV2 + koff + kt * (16 * QST * 2) + patA + p * 32;
                    LDSM4T(vh[2*p][0], vh[2*p][1], vh[2*p+1][0], vh[2*p+1][1], vd);
                }
#pragma unroll
                for (int d = 0; d < 8; d++) MMA_F16(accO[d], pah, vh[d]);
            }
        }
    }

    float i0 = 1.f / l0r, i1 = 1.f / l1r;
    const size_t obase = rbase * DMODEL;
    const int growg = q0 + warp * 16 + frow;
#pragma unroll
    for (int ni = 0; ni < 8; ni++) {
        int col = hc + ni * 8 + fcol;
        *(uint32_t*)&Oh[obase + (size_t)growg * DMODEL + col] =
            f2h2(accO[ni][1] * i0, accO[ni][0] * i0);
        *(uint32_t*)&Oh[obase + (size_t)(growg + 8) * DMODEL + col] =
            f2h2(accO[ni][3] * i1, accO[ni][2] * i1);
    }
}

// ---------------- launch -----------------------------------------------------
extern "C" void kernel_launch(void* const* d_in, const int* in_sizes, int n_in,
                              void* d_out, int out_size)
{
    const float* x  = (const float*)d_in[0];
    const int*   adj = (const int*) d_in[1];
    const float* wq = (const float*)d_in[2];
    const float* bq = (const float*)d_in[3];
    const float* wk = (const float*)d_in[4];
    const float* bk = (const float*)d_in[5];
    const float* wv = (const float*)d_in[6];
    const float* bv = (const float*)d_in[7];
    const float* wo = (const float*)d_in[8];
    const float* bo = (const float*)d_in[9];
    float* out = (float*)d_out;

    __half *gqh, *gkh, *gvh, *gxh, *gah, *gwh;
    uint32_t* gab;
    cudaGetSymbolAddress((void**)&gqh, g_qh);
    cudaGetSymbolAddress((void**)&gkh, g_kh);
    cudaGetSymbolAddress((void**)&gvh, g_vh);
    cudaGetSymbolAddress((void**)&gxh, g_xh);
    cudaGetSymbolAddress((void**)&gah, g_ah);
    cudaGetSymbolAddress((void**)&gwh, g_wh);
    cudaGetSymbolAddress((void**)&gab, g_adjbits);

    cudaFuncSetAttribute(qkv_gemm,
                         cudaFuncAttributeMaxDynamicSharedMemorySize, PIPE64);
    cudaFuncSetAttribute(out_gemm,
                         cudaFuncAttributeMaxDynamicSharedMemorySize, PIPE32);
    cudaFuncSetAttribute(attn_mma,
                         cudaFuncAttributeMaxDynamicSharedMemorySize, ATTN7_SMEM);

    const int WSZ = DMODEL * DMODEL;           // 65536

    prologue<<<NBLK_X + NBLK_W + NBLK_A, 256>>>(
        x, wq, wk, wv, wo, adj, gxh, gwh, gab);

    qkv_gemm<<<dim3(DQKV / 128, MTOT / 128), 256, PIPE64>>>(
        gxh, gwh, bq, bk, bv, gqh, gkh, gvh);

    attn_mma<<<dim3(SEQ / 128, NHEAD, BATCH), 256, ATTN7_SMEM>>>(
        gqh, gkh, gvh, gab, gah);

    out_gemm<<<dim3(DMODEL / 128, MTOT / 128), 256, PIPE32>>>(
        gah, gwh + 3*WSZ, bo, out);
}